// round 12
// baseline (speedup 1.0000x reference)
#include <cuda_runtime.h>
#include <cuda_fp16.h>
#include <math.h>
#include <stdint.h>

// Problem dims
#define K_DIM   4096
#define E_DIM   64
#define M_TOTAL 32768
#define BATCH   4

// ---- GEMM (m16n8k16 fp16x3, 256 thr, 2 CTA/SM, early-STS pipeline) ----
#define BM        128
#define NTHREADS  256
#define KC        32
#define NCHUNK    (K_DIM / KC)            // 128
#define GEMM_GRID (M_TOTAL / BM)          // 256  (single wave at 2 CTA/SM)
// frag stage layout in uint32 units: AH[2][8][32][4] AL BH[2][8][32][2] BL
#define F_AH 0
#define F_AL 2048
#define F_BH 4096
#define F_BL 5120
#define STAGE_U   6144                    // u32 per stage (24KB)
#define GEMM_SMEM (2 * STAGE_U * 4)       // 48KB -> 2 CTAs/SM

// ---- Sinkhorn ----
#define SK_GRID       256
#define ROWS_PB       (M_TOTAL / SK_GRID) // 128
#define BLK_PER_BATCH (SK_GRID / BATCH)   // 64
#define N_ITERS       8

// -------- device scratch --------
__device__ float g_A[(size_t)M_TOTAL * E_DIM];       // 8 MB log-gates
__device__ float g_part[2][SK_GRID * E_DIM * 2];
__device__ unsigned int g_count;
__device__ volatile unsigned int g_gen;

// ======================= helpers =======================
__device__ __forceinline__ void mma_f16(float* d, const uint32_t* a, const uint32_t* b) {
    asm volatile(
        "mma.sync.aligned.m16n8k16.row.col.f32.f16.f16.f32 "
        "{%0,%1,%2,%3}, {%4,%5,%6,%7}, {%8,%9}, {%0,%1,%2,%3};"
        : "+f"(d[0]), "+f"(d[1]), "+f"(d[2]), "+f"(d[3])
        : "r"(a[0]), "r"(a[1]), "r"(a[2]), "r"(a[3]), "r"(b[0]), "r"(b[1]));
}

// split 2 consecutive-k fp32 -> packed f16x2 hi + f16x2 lo (k-even in LOW half)
__device__ __forceinline__ void split2(float v0, float v1, uint32_t& hi, uint32_t& lo) {
    uint32_t h;
    asm("cvt.rn.f16x2.f32 %0, %1, %2;" : "=r"(h) : "f"(v1), "f"(v0));
    __half2 hh = *reinterpret_cast<__half2*>(&h);
    float f0 = __low2float(hh);
    float f1 = __high2float(hh);
    uint32_t l;
    asm("cvt.rn.f16x2.f32 %0, %1, %2;" : "=r"(l) : "f"(v1 - f1), "f"(v0 - f0));
    hi = h;
    lo = l;
}

// ======================= GEMM kernel =======================
// gates = x @ w^T ; g_A = log(max(gates, 1e-6))
// frag layout (verified rounds 6/8/11): A [k2][mt 8][slot^2k2][ea], B [k2][nt 8][slot^2k2][eb]
__global__ void __launch_bounds__(NTHREADS, 2)
gemm_log_kernel(const float* __restrict__ x, const float* __restrict__ w)
{
    extern __shared__ uint32_t sm[];
    const int tid  = threadIdx.x;
    const int lane = tid & 31;
    const int wid  = tid >> 5;               // 0..7
    const int warp_m = wid >> 1;             // 0..3 -> rows warp_m*32
    const int warp_n = wid & 1;              // 0..1 -> cols warp_n*32
    const int m0 = blockIdx.x * BM;

    // loader geometry: 8 float4-cols (KC=32) x 32 row-groups
    const int col4 = tid & 7;
    const int rowg = tid >> 3;               // 0..31
    const float* xp = x + (size_t)(m0 + rowg) * K_DIM + col4 * 4;
    const float* wp = w + (size_t)rowg * K_DIM + col4 * 4;

    // converter fragment coords
    const int kk     = col4 >> 2;
    const int qp     = (col4 & 3) * 2;
    const int q      = qp & 3;
    const int khibit = qp >> 2;
    const int swz    = 2 * kk;

    float4 xv[4], wv[2];
    auto ldg = [&](int kb) {
        const float* a = xp + kb * KC;
        const float* b = wp + kb * KC;
#pragma unroll
        for (int i = 0; i < 4; i++)
            xv[i] = *reinterpret_cast<const float4*>(a + (size_t)(32 * i) * K_DIM);
#pragma unroll
        for (int i = 0; i < 2; i++)
            wv[i] = *reinterpret_cast<const float4*>(b + (size_t)(32 * i) * K_DIM);
    };

    auto sts = [&](uint32_t* fg) {
        // x -> A hi/lo (4 rows per thread: rowg + 32*i)
#pragma unroll
        for (int i = 0; i < 4; i++) {
            const int m = rowg + 32 * i;
            const int g = m & 7, mt = m >> 4, rowbit = (m >> 3) & 1;
            const int ea = rowbit + 2 * khibit;
            const int s0 = (g * 4 + q) ^ swz;
            uint32_t h0, l0, h1, l1;
            split2(xv[i].x, xv[i].y, h0, l0);
            split2(xv[i].z, xv[i].w, h1, l1);
            const int base = ((kk * 8 + mt) * 32 + s0) * 4 + ea;
            fg[F_AH + base]     = h0;
            fg[F_AH + base + 4] = h1;
            fg[F_AL + base]     = l0;
            fg[F_AL + base + 4] = l1;
        }
        // w -> B hi/lo (2 rows per thread)
#pragma unroll
        for (int i = 0; i < 2; i++) {
            const int n = rowg + 32 * i;
            const int g = n & 7, nt = n >> 3;
            const int s0 = (g * 4 + q) ^ swz;
            uint32_t h0, l0, h1, l1;
            split2(wv[i].x, wv[i].y, h0, l0);
            split2(wv[i].z, wv[i].w, h1, l1);
            const int base = ((kk * 8 + nt) * 32 + s0) * 2 + khibit;
            fg[F_BH + base]     = h0;
            fg[F_BH + base + 2] = h1;
            fg[F_BL + base]     = l0;
            fg[F_BL + base + 2] = l1;
        }
    };

    float acc[2][4][4];
#pragma unroll
    for (int i = 0; i < 2; i++)
#pragma unroll
        for (int j = 0; j < 4; j++)
#pragma unroll
            for (int e = 0; e < 4; e++) acc[i][j][e] = 0.f;

    auto mma_stage = [&](const uint32_t* fg) {
#pragma unroll
        for (int k2 = 0; k2 < 2; k2++) {
            const int sl = lane ^ (2 * k2);
            uint4 ah[2], al[2];
#pragma unroll
            for (int i = 0; i < 2; i++) {
                const int mt = warp_m * 2 + i;
                ah[i] = *reinterpret_cast<const uint4*>(&fg[F_AH + ((k2 * 8 + mt) * 32 + sl) * 4]);
                al[i] = *reinterpret_cast<const uint4*>(&fg[F_AL + ((k2 * 8 + mt) * 32 + sl) * 4]);
            }
            uint2 bh[4], bl[4];
#pragma unroll
            for (int j = 0; j < 4; j++) {
                const int nt = warp_n * 4 + j;
                bh[j] = *reinterpret_cast<const uint2*>(&fg[F_BH + ((k2 * 8 + nt) * 32 + sl) * 2]);
                bl[j] = *reinterpret_cast<const uint2*>(&fg[F_BL + ((k2 * 8 + nt) * 32 + sl) * 2]);
            }
#pragma unroll
            for (int i = 0; i < 2; i++)
#pragma unroll
                for (int j = 0; j < 4; j++) {
                    mma_f16(acc[i][j], (const uint32_t*)&ah[i], (const uint32_t*)&bl[j]);
                    mma_f16(acc[i][j], (const uint32_t*)&al[i], (const uint32_t*)&bh[j]);
                    mma_f16(acc[i][j], (const uint32_t*)&ah[i], (const uint32_t*)&bh[j]);
                }
        }
    };

    // ---- pipeline: STS issued EARLY so it drains under the MMA burst ----
    ldg(0);
    sts(sm);              // chunk 0 -> frag 0
    ldg(1);               // chunk 1 -> regs
    __syncthreads();

    for (int kb = 0; kb < NCHUNK; kb++) {
        if (kb + 1 < NCHUNK) sts(sm + ((kb + 1) & 1) * STAGE_U);  // regs(kb+1) -> other buf
        if (kb + 2 < NCHUNK) ldg(kb + 2);                         // next chunk -> regs
        mma_stage(sm + (kb & 1) * STAGE_U);                       // covers the STS drain
        __syncthreads();
    }

    // epilogue: A = log(clip(gate, eps))
    const int gq = lane >> 2, qq = lane & 3;
#pragma unroll
    for (int i = 0; i < 2; i++) {
#pragma unroll
        for (int j = 0; j < 4; j++) {
            const int row0 = m0 + warp_m * 32 + i * 16 + gq;
            const int col  = warp_n * 32 + j * 8 + qq * 2;
            float2 v0, v1;
            v0.x = __logf(fmaxf(acc[i][j][0], 1e-6f));
            v0.y = __logf(fmaxf(acc[i][j][1], 1e-6f));
            v1.x = __logf(fmaxf(acc[i][j][2], 1e-6f));
            v1.y = __logf(fmaxf(acc[i][j][3], 1e-6f));
            *reinterpret_cast<float2*>(&g_A[(size_t)row0 * E_DIM + col]) = v0;
            *reinterpret_cast<float2*>(&g_A[(size_t)(row0 + 8) * E_DIM + col]) = v1;
        }
    }
}

// ======================= persistent Sinkhorn =======================
__device__ __forceinline__ void grid_barrier()
{
    __syncthreads();
    if (threadIdx.x == 0) {
        unsigned int my = g_gen;
        __threadfence();
        if (atomicAdd(&g_count, 1u) == SK_GRID - 1) {
            g_count = 0;
            __threadfence();
            g_gen = my + 1;
        } else {
            while (g_gen == my) { __nanosleep(64); }
        }
        __threadfence();
    }
    __syncthreads();
}

// Invariant: t = A - r[row] - c[e].
__global__ void __launch_bounds__(256, 2)
sinkhorn_kernel(float* __restrict__ out)
{
    extern __shared__ float sA[];            // ROWS_PB * 64 = 32 KB
    __shared__ float r_s[ROWS_PB];
    __shared__ float c_s[E_DIM];
    __shared__ float pm[4 * E_DIM];
    __shared__ float ps[4 * E_DIM];

    const int tid = threadIdx.x;
    const int b   = blockIdx.x / BLK_PER_BATCH;
    const size_t base = (size_t)blockIdx.x * ROWS_PB * E_DIM;

    for (int idx = tid; idx < ROWS_PB * E_DIM; idx += 256)
        sA[idx] = g_A[base + idx];
    if (tid < ROWS_PB) r_s[tid] = 0.f;
    __syncthreads();

    const int e   = tid & 63;
    const int grp = tid >> 6;                // 0..3 -> 32-row slice
    const int row2  = tid >> 1;
    const int half  = tid & 1;

    for (int it = 0; it < N_ITERS; it++) {
        float* part = g_part[it & 1];

        // step 1: per-expert partial LSE over 32-row slice of (A - r)
        {
            const int r0 = grp * 32;
            float M0 = -1e30f, M1 = -1e30f;
#pragma unroll 4
            for (int rr = 0; rr < 32; rr += 2) {
                M0 = fmaxf(M0, sA[(r0 + rr) * 64 + e]     - r_s[r0 + rr]);
                M1 = fmaxf(M1, sA[(r0 + rr + 1) * 64 + e] - r_s[r0 + rr + 1]);
            }
            float M = fmaxf(M0, M1);
            float S0 = 0.f, S1 = 0.f;
#pragma unroll 4
            for (int rr = 0; rr < 32; rr += 2) {
                S0 += __expf(sA[(r0 + rr) * 64 + e]     - r_s[r0 + rr]     - M);
                S1 += __expf(sA[(r0 + rr + 1) * 64 + e] - r_s[r0 + rr + 1] - M);
            }
            pm[grp * 64 + e] = M;
            ps[grp * 64 + e] = S0 + S1;
        }
        __syncthreads();
        if (tid < 64) {
            float M = pm[tid], S = ps[tid];
#pragma unroll
            for (int g = 1; g < 4; g++) {
                float m2 = pm[g * 64 + tid], s2 = ps[g * 64 + tid];
                float nm = fmaxf(M, m2);
                S = S * __expf(M - nm) + s2 * __expf(m2 - nm);
                M = nm;
            }
            part[(blockIdx.x * 64 + tid) * 2 + 0] = M;
            part[(blockIdx.x * 64 + tid) * 2 + 1] = S;
        }
        grid_barrier();

        // combine c over the 64 blocks of this batch (grp handles 16 each)
        {
            float M = -1e30f, S = 0.f;
#pragma unroll
            for (int kk2 = 0; kk2 < 16; kk2++) {
                int blk = b * BLK_PER_BATCH + grp * 16 + kk2;
                float m2 = part[(blk * 64 + e) * 2 + 0];
                float s2 = part[(blk * 64 + e) * 2 + 1];
                float nm = fmaxf(M, m2);
                S = S * __expf(M - nm) + s2 * __expf(m2 - nm);
                M = nm;
            }
            pm[grp * 64 + e] = M;
            ps[grp * 64 + e] = S;
        }
        __syncthreads();
        if (tid < 64) {
            float M = pm[tid], S = ps[tid];
#pragma unroll
            for (int g = 1; g < 4; g++) {
                float m2 = pm[g * 64 + tid], s2 = ps[g * 64 + tid];
                float nm = fmaxf(M, m2);
                S = S * __expf(M - nm) + s2 * __expf(m2 - nm);
                M = nm;
            }
            c_s[tid] = M + __logf(S);
        }
        __syncthreads();

        // step 2: r[row] = LSE_e(A - c); thread pair splits the 64 experts
        {
            const float* rowp = &sA[row2 * 64];
            float M = -1e30f;
#pragma unroll 8
            for (int j = 0; j < 32; j++) {
                int e2 = (half * 32 + j + row2) & 63;
                M = fmaxf(M, rowp[e2] - c_s[e2]);
            }
            float S = 0.f;
#pragma unroll 8
            for (int j = 0; j < 32; j++) {
                int e2 = (half * 32 + j + row2) & 63;
                S += __expf(rowp[e2] - c_s[e2] - M);
            }
            float om = __shfl_xor_sync(0xFFFFFFFFu, M, 1);
            float os = __shfl_xor_sync(0xFFFFFFFFu, S, 1);
            float nm = fmaxf(M, om);
            S = S * __expf(M - nm) + os * __expf(om - nm);
            r_s[row2] = nm + __logf(S);
        }
        __syncthreads();
    }

    // final: out = exp(A - r - c)
    for (int idx = tid; idx < ROWS_PB * E_DIM; idx += 256) {
        int row = idx >> 6, ee = idx & 63;
        out[base + idx] = __expf(sA[idx] - r_s[row] - c_s[ee]);
    }
}

// noop: shifts ncu capture parity so the GEMM gets profiled
__global__ void noop_kernel() {}

// ======================= launch =======================
extern "C" void kernel_launch(void* const* d_in, const int* in_sizes, int n_in,
                              void* d_out, int out_size)
{
    (void)in_sizes; (void)n_in; (void)out_size;
    const float* x = (const float*)d_in[0];       // [4,8192,4096] fp32
    const float* w = (const float*)d_in[1];       // [64,4096] fp32
    float* out = (float*)d_out;                   // [4,8192,64] fp32

    cudaFuncSetAttribute(gemm_log_kernel,
                         cudaFuncAttributeMaxDynamicSharedMemorySize, GEMM_SMEM);
    gemm_log_kernel<<<GEMM_GRID, NTHREADS, GEMM_SMEM>>>(x, w);

    cudaFuncSetAttribute(sinkhorn_kernel,
                         cudaFuncAttributeMaxDynamicSharedMemorySize,
                         ROWS_PB * E_DIM * (int)sizeof(float));
    sinkhorn_kernel<<<SK_GRID, 256, ROWS_PB * E_DIM * sizeof(float)>>>(out);

    noop_kernel<<<1, 32>>>();
}

// round 13
// speedup vs baseline: 1.1073x; 1.1073x over previous
#include <cuda_runtime.h>
#include <cuda_fp16.h>
#include <math.h>
#include <stdint.h>

// Problem dims
#define K_DIM   4096
#define E_DIM   64
#define M_TOTAL 32768
#define BATCH   4

// ---- GEMM (m16n8k16 fp16x3, A direct-from-global, B via smem) ----
#define BM        128
#define NTHREADS  256
#define KC        32
#define NCHUNK    (K_DIM / KC)            // 128
#define GEMM_GRID (M_TOTAL / BM)          // 256 (single wave at 2 CTA/SM)
// B frag stage (u32): BH[2 k2][8 nt][32 slot][2 eb] ; BL same
#define F_BH 0
#define F_BL 1024
#define STAGE_U   2048                    // 8KB per stage
#define GEMM_SMEM (2 * STAGE_U * 4)       // 16KB

// ---- Sinkhorn ----
#define SK_GRID       256
#define ROWS_PB       (M_TOTAL / SK_GRID) // 128
#define BLK_PER_BATCH (SK_GRID / BATCH)   // 64
#define N_ITERS       8

// -------- device scratch --------
__device__ float g_A[(size_t)M_TOTAL * E_DIM];       // 8 MB log-gates
__device__ float g_part[2][SK_GRID * E_DIM * 2];
__device__ unsigned int g_count;
__device__ volatile unsigned int g_gen;

// ======================= helpers =======================
__device__ __forceinline__ void mma_f16(float* d, const uint32_t* a, const uint32_t* b) {
    asm volatile(
        "mma.sync.aligned.m16n8k16.row.col.f32.f16.f16.f32 "
        "{%0,%1,%2,%3}, {%4,%5,%6,%7}, {%8,%9}, {%0,%1,%2,%3};"
        : "+f"(d[0]), "+f"(d[1]), "+f"(d[2]), "+f"(d[3])
        : "r"(a[0]), "r"(a[1]), "r"(a[2]), "r"(a[3]), "r"(b[0]), "r"(b[1]));
}

// split 2 consecutive-k fp32 -> packed f16x2 hi + f16x2 lo (k-even in LOW half)
__device__ __forceinline__ void split2(float v0, float v1, uint32_t& hi, uint32_t& lo) {
    uint32_t h;
    asm("cvt.rn.f16x2.f32 %0, %1, %2;" : "=r"(h) : "f"(v1), "f"(v0));
    __half2 hh = *reinterpret_cast<__half2*>(&h);
    float f0 = __low2float(hh);
    float f1 = __high2float(hh);
    uint32_t l;
    asm("cvt.rn.f16x2.f32 %0, %1, %2;" : "=r"(l) : "f"(v1 - f1), "f"(v0 - f0));
    hi = h;
    lo = l;
}

// ======================= GEMM kernel =======================
// gates = x @ w^T ; g_A = log(max(gates, 1e-6))
// A fragments loaded warp-direct from global (8B/lane, 32B/sector-exact).
// B frag layout (verified rounds 6-12): [k2][nt 8][slot^2k2][eb]
__global__ void __launch_bounds__(NTHREADS, 2)
gemm_log_kernel(const float* __restrict__ x, const float* __restrict__ w)
{
    extern __shared__ uint32_t sm[];
    const int tid  = threadIdx.x;
    const int lane = tid & 31;
    const int wid  = tid >> 5;               // 0..7
    const int warp_m = wid >> 1;             // 0..3 -> rows warp_m*32
    const int warp_n = wid & 1;              // 0..1 -> cols warp_n*32
    const int m0 = blockIdx.x * BM;

    const int g = lane >> 2, q = lane & 3;   // mma lane coords

    // ---- A direct-load base (this thread's fragment elements) ----
    const float* abase = x + (size_t)(m0 + warp_m * 32 + g) * K_DIM + 2 * q;

    // raw A for one stage: [k2][mt][e], e = (rowbit) + 2*(khibit)
    float2 araw[2][2][4];
    auto ldg_a = [&](int kb) {
        const float* p = abase + kb * KC;
#pragma unroll
        for (int k2 = 0; k2 < 2; k2++)
#pragma unroll
            for (int mt = 0; mt < 2; mt++)
#pragma unroll
                for (int e = 0; e < 4; e++) {
                    const size_t roff = (size_t)(mt * 16 + (e & 1) * 8) * K_DIM;
                    araw[k2][mt][e] = *reinterpret_cast<const float2*>(
                        p + roff + k2 * 16 + (e >> 1) * 8);
                }
    };

    // converted A fragments for current stage
    uint4 ah[2][2], al[2][2];                // [k2][mt]
    auto convert_a = [&]() {
#pragma unroll
        for (int k2 = 0; k2 < 2; k2++)
#pragma unroll
            for (int mt = 0; mt < 2; mt++) {
                uint32_t h, l;
                split2(araw[k2][mt][0].x, araw[k2][mt][0].y, h, l); ah[k2][mt].x = h; al[k2][mt].x = l;
                split2(araw[k2][mt][1].x, araw[k2][mt][1].y, h, l); ah[k2][mt].y = h; al[k2][mt].y = l;
                split2(araw[k2][mt][2].x, araw[k2][mt][2].y, h, l); ah[k2][mt].z = h; al[k2][mt].z = l;
                split2(araw[k2][mt][3].x, araw[k2][mt][3].y, h, l); ah[k2][mt].w = h; al[k2][mt].w = l;
            }
    };

    // ---- B (w) loader: 256 threads, 8KB/stage ----
    const int col4 = tid & 7;                // float4 col in KC
    const int rowg = tid >> 3;               // 0..31
    const float* wp = w + (size_t)rowg * K_DIM + col4 * 4;
    const int kk     = col4 >> 2;
    const int qp     = (col4 & 3) * 2;
    const int qb     = qp & 3;
    const int khibit = qp >> 2;
    const int swz    = 2 * kk;

    float4 wv[2];
    auto ldg_w = [&](int kb) {
        const float* b = wp + kb * KC;
#pragma unroll
        for (int i = 0; i < 2; i++)
            wv[i] = *reinterpret_cast<const float4*>(b + (size_t)(32 * i) * K_DIM);
    };
    auto sts_w = [&](uint32_t* fg) {
#pragma unroll
        for (int i = 0; i < 2; i++) {
            const int n = rowg + 32 * i;
            const int gg = n & 7, nt = n >> 3;
            const int s0 = (gg * 4 + qb) ^ swz;
            uint32_t h0, l0, h1, l1;
            split2(wv[i].x, wv[i].y, h0, l0);
            split2(wv[i].z, wv[i].w, h1, l1);
            const int base = ((kk * 8 + nt) * 32 + s0) * 2 + khibit;
            fg[F_BH + base]     = h0;
            fg[F_BH + base + 2] = h1;
            fg[F_BL + base]     = l0;
            fg[F_BL + base + 2] = l1;
        }
    };

    float acc[2][4][4];
#pragma unroll
    for (int i = 0; i < 2; i++)
#pragma unroll
        for (int j = 0; j < 4; j++)
#pragma unroll
            for (int e = 0; e < 4; e++) acc[i][j][e] = 0.f;

    auto mma_stage = [&](const uint32_t* fg) {
#pragma unroll
        for (int k2 = 0; k2 < 2; k2++) {
            const int sl = lane ^ (2 * k2);
            uint2 bh[4], bl[4];
#pragma unroll
            for (int j = 0; j < 4; j++) {
                const int nt = warp_n * 4 + j;
                bh[j] = *reinterpret_cast<const uint2*>(&fg[F_BH + ((k2 * 8 + nt) * 32 + sl) * 2]);
                bl[j] = *reinterpret_cast<const uint2*>(&fg[F_BL + ((k2 * 8 + nt) * 32 + sl) * 2]);
            }
#pragma unroll
            for (int i = 0; i < 2; i++)
#pragma unroll
                for (int j = 0; j < 4; j++) {
                    mma_f16(acc[i][j], (const uint32_t*)&ah[k2][i], (const uint32_t*)&bl[j]);
                    mma_f16(acc[i][j], (const uint32_t*)&al[k2][i], (const uint32_t*)&bh[j]);
                    mma_f16(acc[i][j], (const uint32_t*)&ah[k2][i], (const uint32_t*)&bh[j]);
                }
        }
    };

    // ---- pipeline ----
    ldg_a(0);                 // A raw for stage 0
    ldg_w(0);
    sts_w(sm);                // w chunk 0 -> buf 0
    ldg_w(1);                 // w chunk 1 -> regs
    __syncthreads();

    for (int kb = 0; kb < NCHUNK; kb++) {
        convert_a();                                  // araw(kb) -> ah/al, araw free
        if (kb + 1 < NCHUNK) ldg_a(kb + 1);           // refill araw (next stage)
        if (kb + 1 < NCHUNK) sts_w(sm + ((kb + 1) & 1) * STAGE_U);
        if (kb + 2 < NCHUNK) ldg_w(kb + 2);
        mma_stage(sm + (kb & 1) * STAGE_U);
        __syncthreads();
    }

    // epilogue: A = log(clip(gate, eps))
    const int gq = lane >> 2, qq = lane & 3;
#pragma unroll
    for (int i = 0; i < 2; i++) {
#pragma unroll
        for (int j = 0; j < 4; j++) {
            const int row0 = m0 + warp_m * 32 + i * 16 + gq;
            const int col  = warp_n * 32 + j * 8 + qq * 2;
            float2 v0, v1;
            v0.x = __logf(fmaxf(acc[i][j][0], 1e-6f));
            v0.y = __logf(fmaxf(acc[i][j][1], 1e-6f));
            v1.x = __logf(fmaxf(acc[i][j][2], 1e-6f));
            v1.y = __logf(fmaxf(acc[i][j][3], 1e-6f));
            *reinterpret_cast<float2*>(&g_A[(size_t)row0 * E_DIM + col]) = v0;
            *reinterpret_cast<float2*>(&g_A[(size_t)(row0 + 8) * E_DIM + col]) = v1;
        }
    }
}

// ======================= persistent Sinkhorn =======================
__device__ __forceinline__ void grid_barrier()
{
    __syncthreads();
    if (threadIdx.x == 0) {
        unsigned int my = g_gen;
        __threadfence();
        if (atomicAdd(&g_count, 1u) == SK_GRID - 1) {
            g_count = 0;
            __threadfence();
            g_gen = my + 1;
        } else {
            while (g_gen == my) { __nanosleep(64); }
        }
        __threadfence();
    }
    __syncthreads();
}

// Invariant: t = A - r[row] - c[e].
__global__ void __launch_bounds__(256, 2)
sinkhorn_kernel(float* __restrict__ out)
{
    extern __shared__ float sA[];            // ROWS_PB * 64 = 32 KB
    __shared__ float r_s[ROWS_PB];
    __shared__ float c_s[E_DIM];
    __shared__ float pm[4 * E_DIM];
    __shared__ float ps[4 * E_DIM];

    const int tid = threadIdx.x;
    const int b   = blockIdx.x / BLK_PER_BATCH;
    const size_t base = (size_t)blockIdx.x * ROWS_PB * E_DIM;

    for (int idx = tid; idx < ROWS_PB * E_DIM; idx += 256)
        sA[idx] = g_A[base + idx];
    if (tid < ROWS_PB) r_s[tid] = 0.f;
    __syncthreads();

    const int e   = tid & 63;
    const int grp = tid >> 6;                // 0..3 -> 32-row slice
    const int row2  = tid >> 1;
    const int half  = tid & 1;

    for (int it = 0; it < N_ITERS; it++) {
        float* part = g_part[it & 1];

        // step 1: per-expert partial LSE over 32-row slice of (A - r)
        {
            const int r0 = grp * 32;
            float M0 = -1e30f, M1 = -1e30f;
#pragma unroll 4
            for (int rr = 0; rr < 32; rr += 2) {
                M0 = fmaxf(M0, sA[(r0 + rr) * 64 + e]     - r_s[r0 + rr]);
                M1 = fmaxf(M1, sA[(r0 + rr + 1) * 64 + e] - r_s[r0 + rr + 1]);
            }
            float M = fmaxf(M0, M1);
            float S0 = 0.f, S1 = 0.f;
#pragma unroll 4
            for (int rr = 0; rr < 32; rr += 2) {
                S0 += __expf(sA[(r0 + rr) * 64 + e]     - r_s[r0 + rr]     - M);
                S1 += __expf(sA[(r0 + rr + 1) * 64 + e] - r_s[r0 + rr + 1] - M);
            }
            pm[grp * 64 + e] = M;
            ps[grp * 64 + e] = S0 + S1;
        }
        __syncthreads();
        if (tid < 64) {
            float M = pm[tid], S = ps[tid];
#pragma unroll
            for (int g2 = 1; g2 < 4; g2++) {
                float m2 = pm[g2 * 64 + tid], s2 = ps[g2 * 64 + tid];
                float nm = fmaxf(M, m2);
                S = S * __expf(M - nm) + s2 * __expf(m2 - nm);
                M = nm;
            }
            part[(blockIdx.x * 64 + tid) * 2 + 0] = M;
            part[(blockIdx.x * 64 + tid) * 2 + 1] = S;
        }
        grid_barrier();

        // combine c over the 64 blocks of this batch (grp handles 16 each)
        {
            float M = -1e30f, S = 0.f;
#pragma unroll
            for (int kk2 = 0; kk2 < 16; kk2++) {
                int blk = b * BLK_PER_BATCH + grp * 16 + kk2;
                float m2 = part[(blk * 64 + e) * 2 + 0];
                float s2 = part[(blk * 64 + e) * 2 + 1];
                float nm = fmaxf(M, m2);
                S = S * __expf(M - nm) + s2 * __expf(m2 - nm);
                M = nm;
            }
            pm[grp * 64 + e] = M;
            ps[grp * 64 + e] = S;
        }
        __syncthreads();
        if (tid < 64) {
            float M = pm[tid], S = ps[tid];
#pragma unroll
            for (int g2 = 1; g2 < 4; g2++) {
                float m2 = pm[g2 * 64 + tid], s2 = ps[g2 * 64 + tid];
                float nm = fmaxf(M, m2);
                S = S * __expf(M - nm) + s2 * __expf(m2 - nm);
                M = nm;
            }
            c_s[tid] = M + __logf(S);
        }
        __syncthreads();

        // step 2: r[row] = LSE_e(A - c); thread pair splits the 64 experts
        {
            const float* rowp = &sA[row2 * 64];
            float M = -1e30f;
#pragma unroll 8
            for (int j = 0; j < 32; j++) {
                int e2 = (half * 32 + j + row2) & 63;
                M = fmaxf(M, rowp[e2] - c_s[e2]);
            }
            float S = 0.f;
#pragma unroll 8
            for (int j = 0; j < 32; j++) {
                int e2 = (half * 32 + j + row2) & 63;
                S += __expf(rowp[e2] - c_s[e2] - M);
            }
            float om = __shfl_xor_sync(0xFFFFFFFFu, M, 1);
            float os = __shfl_xor_sync(0xFFFFFFFFu, S, 1);
            float nm = fmaxf(M, om);
            S = S * __expf(M - nm) + os * __expf(om - nm);
            r_s[row2] = nm + __logf(S);
        }
        __syncthreads();
    }

    // final: out = exp(A - r - c)
    for (int idx = tid; idx < ROWS_PB * E_DIM; idx += 256) {
        int row = idx >> 6, ee = idx & 63;
        out[base + idx] = __expf(sA[idx] - r_s[row] - c_s[ee]);
    }
}

// noop: shifts ncu capture parity so the GEMM gets profiled
__global__ void noop_kernel() {}

// ======================= launch =======================
extern "C" void kernel_launch(void* const* d_in, const int* in_sizes, int n_in,
                              void* d_out, int out_size)
{
    (void)in_sizes; (void)n_in; (void)out_size;
    const float* x = (const float*)d_in[0];       // [4,8192,4096] fp32
    const float* w = (const float*)d_in[1];       // [64,4096] fp32
    float* out = (float*)d_out;                   // [4,8192,64] fp32

    cudaFuncSetAttribute(gemm_log_kernel,
                         cudaFuncAttributeMaxDynamicSharedMemorySize, GEMM_SMEM);
    gemm_log_kernel<<<GEMM_GRID, NTHREADS, GEMM_SMEM>>>(x, w);

    cudaFuncSetAttribute(sinkhorn_kernel,
                         cudaFuncAttributeMaxDynamicSharedMemorySize,
                         ROWS_PB * E_DIM * (int)sizeof(float));
    sinkhorn_kernel<<<SK_GRID, 256, ROWS_PB * E_DIM * sizeof(float)>>>(out);

    noop_kernel<<<1, 32>>>();
}

// round 14
// speedup vs baseline: 1.3245x; 1.1962x over previous
#include <cuda_runtime.h>
#include <cuda_fp16.h>
#include <math.h>
#include <stdint.h>

// Problem dims
#define K_DIM   4096
#define E_DIM   64
#define M_TOTAL 32768
#define BATCH   4

// ---- GEMM (m16n8k16, 2-term asymmetric split: x=xh, w=wh+wl) ----
#define BM        128
#define NTHREADS  256
#define KC        32
#define NCHUNK    (K_DIM / KC)            // 128
#define GEMM_GRID (M_TOTAL / BM)          // 256 (single wave at 2 CTA/SM)
// frag stage (u32): AH[2 k2][8 mt][32 slot][4 ea], BH[2][8][32][2], BL same
#define F_AH 0
#define F_BH 2048
#define F_BL 3072
#define STAGE_U   4096                    // 16KB per stage
#define GEMM_SMEM (2 * STAGE_U * 4)       // 32KB -> 2 CTAs/SM

// ---- Sinkhorn ----
#define SK_GRID       256
#define ROWS_PB       (M_TOTAL / SK_GRID) // 128
#define BLK_PER_BATCH (SK_GRID / BATCH)   // 64
#define N_ITERS       8

// -------- device scratch --------
__device__ float g_A[(size_t)M_TOTAL * E_DIM];       // 8 MB log-gates
__device__ float g_part[2][SK_GRID * E_DIM * 2];
__device__ unsigned int g_count;
__device__ volatile unsigned int g_gen;

// ======================= helpers =======================
__device__ __forceinline__ void mma_f16(float* d, const uint32_t* a, const uint32_t* b) {
    asm volatile(
        "mma.sync.aligned.m16n8k16.row.col.f32.f16.f16.f32 "
        "{%0,%1,%2,%3}, {%4,%5,%6,%7}, {%8,%9}, {%0,%1,%2,%3};"
        : "+f"(d[0]), "+f"(d[1]), "+f"(d[2]), "+f"(d[3])
        : "r"(a[0]), "r"(a[1]), "r"(a[2]), "r"(a[3]), "r"(b[0]), "r"(b[1]));
}

// pack 2 fp32 -> f16x2 (rn), k-even in LOW half
__device__ __forceinline__ uint32_t pack2(float v0, float v1) {
    uint32_t h;
    asm("cvt.rn.f16x2.f32 %0, %1, %2;" : "=r"(h) : "f"(v1), "f"(v0));
    return h;
}

// split 2 fp32 -> f16x2 hi + f16x2 lo (exact residual)
__device__ __forceinline__ void split2(float v0, float v1, uint32_t& hi, uint32_t& lo) {
    uint32_t h = pack2(v0, v1);
    __half2 hh = *reinterpret_cast<__half2*>(&h);
    float f0 = __low2float(hh);
    float f1 = __high2float(hh);
    lo = pack2(v0 - f0, v1 - f1);
    hi = h;
}

// ======================= GEMM kernel =======================
// gates = xh @ (wh + wl)^T ; g_A = log(max(gates, 1e-6))
// frag layout (verified rounds 6-13): A [k2][mt 8][slot^2k2][ea], B [k2][nt 8][slot^2k2][eb]
__global__ void __launch_bounds__(NTHREADS, 2)
gemm_log_kernel(const float* __restrict__ x, const float* __restrict__ w)
{
    extern __shared__ uint32_t sm[];
    const int tid  = threadIdx.x;
    const int lane = tid & 31;
    const int wid  = tid >> 5;               // 0..7
    const int warp_m = wid >> 1;             // 0..3 -> rows warp_m*32
    const int warp_n = wid & 1;              // 0..1 -> cols warp_n*32
    const int m0 = blockIdx.x * BM;

    // loader geometry: 8 float4-cols (KC=32) x 32 row-groups
    const int col4 = tid & 7;
    const int rowg = tid >> 3;               // 0..31
    const float* xp = x + (size_t)(m0 + rowg) * K_DIM + col4 * 4;
    const float* wp = w + (size_t)rowg * K_DIM + col4 * 4;

    // converter fragment coords
    const int kk     = col4 >> 2;
    const int qp     = (col4 & 3) * 2;
    const int q      = qp & 3;
    const int khibit = qp >> 2;
    const int swz    = 2 * kk;

    float4 xv[4], wv[2];
    auto ldg = [&](int kb) {
        const float* a = xp + kb * KC;
        const float* b = wp + kb * KC;
#pragma unroll
        for (int i = 0; i < 4; i++)
            xv[i] = *reinterpret_cast<const float4*>(a + (size_t)(32 * i) * K_DIM);
#pragma unroll
        for (int i = 0; i < 2; i++)
            wv[i] = *reinterpret_cast<const float4*>(b + (size_t)(32 * i) * K_DIM);
    };

    auto sts = [&](uint32_t* fg) {
        // x -> A hi only (4 rows per thread: rowg + 32*i)
#pragma unroll
        for (int i = 0; i < 4; i++) {
            const int m = rowg + 32 * i;
            const int g = m & 7, mt = m >> 4, rowbit = (m >> 3) & 1;
            const int ea = rowbit + 2 * khibit;
            const int s0 = (g * 4 + q) ^ swz;
            const int base = ((kk * 8 + mt) * 32 + s0) * 4 + ea;
            fg[F_AH + base]     = pack2(xv[i].x, xv[i].y);
            fg[F_AH + base + 4] = pack2(xv[i].z, xv[i].w);
        }
        // w -> B hi/lo (2 rows per thread)
#pragma unroll
        for (int i = 0; i < 2; i++) {
            const int n = rowg + 32 * i;
            const int g = n & 7, nt = n >> 3;
            const int s0 = (g * 4 + q) ^ swz;
            uint32_t h0, l0, h1, l1;
            split2(wv[i].x, wv[i].y, h0, l0);
            split2(wv[i].z, wv[i].w, h1, l1);
            const int base = ((kk * 8 + nt) * 32 + s0) * 2 + khibit;
            fg[F_BH + base]     = h0;
            fg[F_BH + base + 2] = h1;
            fg[F_BL + base]     = l0;
            fg[F_BL + base + 2] = l1;
        }
    };

    float acc[2][4][4];
#pragma unroll
    for (int i = 0; i < 2; i++)
#pragma unroll
        for (int j = 0; j < 4; j++)
#pragma unroll
            for (int e = 0; e < 4; e++) acc[i][j][e] = 0.f;

    auto mma_stage = [&](const uint32_t* fg) {
#pragma unroll
        for (int k2 = 0; k2 < 2; k2++) {
            const int sl = lane ^ (2 * k2);
            uint4 ah[2];
#pragma unroll
            for (int i = 0; i < 2; i++) {
                const int mt = warp_m * 2 + i;
                ah[i] = *reinterpret_cast<const uint4*>(&fg[F_AH + ((k2 * 8 + mt) * 32 + sl) * 4]);
            }
            uint2 bh[4], bl[4];
#pragma unroll
            for (int j = 0; j < 4; j++) {
                const int nt = warp_n * 4 + j;
                bh[j] = *reinterpret_cast<const uint2*>(&fg[F_BH + ((k2 * 8 + nt) * 32 + sl) * 2]);
                bl[j] = *reinterpret_cast<const uint2*>(&fg[F_BL + ((k2 * 8 + nt) * 32 + sl) * 2]);
            }
#pragma unroll
            for (int i = 0; i < 2; i++)
#pragma unroll
                for (int j = 0; j < 4; j++) {
                    mma_f16(acc[i][j], (const uint32_t*)&ah[i], (const uint32_t*)&bl[j]);
                    mma_f16(acc[i][j], (const uint32_t*)&ah[i], (const uint32_t*)&bh[j]);
                }
        }
    };

    // ---- pipeline (R12-verified ring: regs hold kb+1; frag[kb&1] holds kb) ----
    ldg(0);
    sts(sm);              // chunk 0 -> buf 0
    ldg(1);               // chunk 1 -> regs
    __syncthreads();

    for (int kb = 0; kb < NCHUNK; kb++) {
        if (kb + 1 < NCHUNK) sts(sm + ((kb + 1) & 1) * STAGE_U);  // regs(kb+1) -> other buf
        if (kb + 2 < NCHUNK) ldg(kb + 2);                         // next chunk -> regs
        mma_stage(sm + (kb & 1) * STAGE_U);
        __syncthreads();
    }

    // epilogue: A = log(clip(gate, eps))
    const int gq = lane >> 2, qq = lane & 3;
#pragma unroll
    for (int i = 0; i < 2; i++) {
#pragma unroll
        for (int j = 0; j < 4; j++) {
            const int row0 = m0 + warp_m * 32 + i * 16 + gq;
            const int col  = warp_n * 32 + j * 8 + qq * 2;
            float2 v0, v1;
            v0.x = __logf(fmaxf(acc[i][j][0], 1e-6f));
            v0.y = __logf(fmaxf(acc[i][j][1], 1e-6f));
            v1.x = __logf(fmaxf(acc[i][j][2], 1e-6f));
            v1.y = __logf(fmaxf(acc[i][j][3], 1e-6f));
            *reinterpret_cast<float2*>(&g_A[(size_t)row0 * E_DIM + col]) = v0;
            *reinterpret_cast<float2*>(&g_A[(size_t)(row0 + 8) * E_DIM + col]) = v1;
        }
    }
}

// ======================= persistent Sinkhorn =======================
__device__ __forceinline__ void grid_barrier()
{
    __syncthreads();
    if (threadIdx.x == 0) {
        unsigned int my = g_gen;
        __threadfence();
        if (atomicAdd(&g_count, 1u) == SK_GRID - 1) {
            g_count = 0;
            __threadfence();
            g_gen = my + 1;
        } else {
            while (g_gen == my) { __nanosleep(64); }
        }
        __threadfence();
    }
    __syncthreads();
}

// Invariant: t = A - r[row] - c[e].
__global__ void __launch_bounds__(256, 2)
sinkhorn_kernel(float* __restrict__ out)
{
    extern __shared__ float sA[];            // ROWS_PB * 64 = 32 KB
    __shared__ float r_s[ROWS_PB];
    __shared__ float c_s[E_DIM];
    __shared__ float pm[4 * E_DIM];
    __shared__ float ps[4 * E_DIM];

    const int tid = threadIdx.x;
    const int b   = blockIdx.x / BLK_PER_BATCH;
    const size_t base = (size_t)blockIdx.x * ROWS_PB * E_DIM;

    for (int idx = tid; idx < ROWS_PB * E_DIM; idx += 256)
        sA[idx] = g_A[base + idx];
    if (tid < ROWS_PB) r_s[tid] = 0.f;
    __syncthreads();

    const int e   = tid & 63;
    const int grp = tid >> 6;                // 0..3 -> 32-row slice
    const int row2  = tid >> 1;
    const int half  = tid & 1;

    for (int it = 0; it < N_ITERS; it++) {
        float* part = g_part[it & 1];

        // step 1: per-expert partial LSE over 32-row slice of (A - r)
        {
            const int r0 = grp * 32;
            float M0 = -1e30f, M1 = -1e30f;
#pragma unroll 4
            for (int rr = 0; rr < 32; rr += 2) {
                M0 = fmaxf(M0, sA[(r0 + rr) * 64 + e]     - r_s[r0 + rr]);
                M1 = fmaxf(M1, sA[(r0 + rr + 1) * 64 + e] - r_s[r0 + rr + 1]);
            }
            float M = fmaxf(M0, M1);
            float S0 = 0.f, S1 = 0.f;
#pragma unroll 4
            for (int rr = 0; rr < 32; rr += 2) {
                S0 += __expf(sA[(r0 + rr) * 64 + e]     - r_s[r0 + rr]     - M);
                S1 += __expf(sA[(r0 + rr + 1) * 64 + e] - r_s[r0 + rr + 1] - M);
            }
            pm[grp * 64 + e] = M;
            ps[grp * 64 + e] = S0 + S1;
        }
        __syncthreads();
        if (tid < 64) {
            float M = pm[tid], S = ps[tid];
#pragma unroll
            for (int g2 = 1; g2 < 4; g2++) {
                float m2 = pm[g2 * 64 + tid], s2 = ps[g2 * 64 + tid];
                float nm = fmaxf(M, m2);
                S = S * __expf(M - nm) + s2 * __expf(m2 - nm);
                M = nm;
            }
            part[(blockIdx.x * 64 + tid) * 2 + 0] = M;
            part[(blockIdx.x * 64 + tid) * 2 + 1] = S;
        }
        grid_barrier();

        // combine c over the 64 blocks of this batch (grp handles 16 each)
        {
            float M = -1e30f, S = 0.f;
#pragma unroll
            for (int kk2 = 0; kk2 < 16; kk2++) {
                int blk = b * BLK_PER_BATCH + grp * 16 + kk2;
                float m2 = part[(blk * 64 + e) * 2 + 0];
                float s2 = part[(blk * 64 + e) * 2 + 1];
                float nm = fmaxf(M, m2);
                S = S * __expf(M - nm) + s2 * __expf(m2 - nm);
                M = nm;
            }
            pm[grp * 64 + e] = M;
            ps[grp * 64 + e] = S;
        }
        __syncthreads();
        if (tid < 64) {
            float M = pm[tid], S = ps[tid];
#pragma unroll
            for (int g2 = 1; g2 < 4; g2++) {
                float m2 = pm[g2 * 64 + tid], s2 = ps[g2 * 64 + tid];
                float nm = fmaxf(M, m2);
                S = S * __expf(M - nm) + s2 * __expf(m2 - nm);
                M = nm;
            }
            c_s[tid] = M + __logf(S);
        }
        __syncthreads();

        // step 2: r[row] = LSE_e(A - c); thread pair splits the 64 experts
        {
            const float* rowp = &sA[row2 * 64];
            float M = -1e30f;
#pragma unroll 8
            for (int j = 0; j < 32; j++) {
                int e2 = (half * 32 + j + row2) & 63;
                M = fmaxf(M, rowp[e2] - c_s[e2]);
            }
            float S = 0.f;
#pragma unroll 8
            for (int j = 0; j < 32; j++) {
                int e2 = (half * 32 + j + row2) & 63;
                S += __expf(rowp[e2] - c_s[e2] - M);
            }
            float om = __shfl_xor_sync(0xFFFFFFFFu, M, 1);
            float os = __shfl_xor_sync(0xFFFFFFFFu, S, 1);
            float nm = fmaxf(M, om);
            S = S * __expf(M - nm) + os * __expf(om - nm);
            r_s[row2] = nm + __logf(S);
        }
        __syncthreads();
    }

    // final: out = exp(A - r - c)
    for (int idx = tid; idx < ROWS_PB * E_DIM; idx += 256) {
        int row = idx >> 6, ee = idx & 63;
        out[base + idx] = __expf(sA[idx] - r_s[row] - c_s[ee]);
    }
}

// noop: shifts ncu capture parity so the GEMM gets profiled
__global__ void noop_kernel() {}

// ======================= launch =======================
extern "C" void kernel_launch(void* const* d_in, const int* in_sizes, int n_in,
                              void* d_out, int out_size)
{
    (void)in_sizes; (void)n_in; (void)out_size;
    const float* x = (const float*)d_in[0];       // [4,8192,4096] fp32
    const float* w = (const float*)d_in[1];       // [64,4096] fp32
    float* out = (float*)d_out;                   // [4,8192,64] fp32

    cudaFuncSetAttribute(gemm_log_kernel,
                         cudaFuncAttributeMaxDynamicSharedMemorySize, GEMM_SMEM);
    gemm_log_kernel<<<GEMM_GRID, NTHREADS, GEMM_SMEM>>>(x, w);

    cudaFuncSetAttribute(sinkhorn_kernel,
                         cudaFuncAttributeMaxDynamicSharedMemorySize,
                         ROWS_PB * E_DIM * (int)sizeof(float));
    sinkhorn_kernel<<<SK_GRID, 256, ROWS_PB * E_DIM * sizeof(float)>>>(out);

    noop_kernel<<<1, 32>>>();
}

// round 17
// speedup vs baseline: 1.3590x; 1.0261x over previous
#include <cuda_runtime.h>
#include <cuda_fp16.h>
#include <math.h>
#include <stdint.h>

// Problem dims
#define K_DIM   4096
#define E_DIM   64
#define M_TOTAL 32768
#define BATCH   4

// ---- GEMM (m16n8k16, 2-term split, BM=256, 8 warps, 1 CTA/SM) ----
#define BM        256
#define NTHREADS  256
#define KC        32
#define NCHUNK    (K_DIM / KC)            // 128
#define GEMM_GRID (M_TOTAL / BM)          // 128
// frag stage (u32): AH[2 k2][16 mt][32 slot][4 ea], BH[2][8][32][2], BL same
#define F_AH 0
#define F_BH 4096
#define F_BL 5120
#define STAGE_U   6144                    // 24KB per stage
#define GEMM_SMEM (2 * STAGE_U * 4)       // 48KB

// ---- Sinkhorn ----
#define SK_GRID       256
#define ROWS_PB       (M_TOTAL / SK_GRID) // 128
#define BLK_PER_BATCH (SK_GRID / BATCH)   // 64
#define N_ITERS       8

// -------- device scratch --------
__device__ float g_A[(size_t)M_TOTAL * E_DIM];       // 8 MB log-gates
__device__ float g_part[2][SK_GRID * E_DIM * 2];
__device__ unsigned int g_count;
__device__ volatile unsigned int g_gen;

// ======================= helpers =======================
__device__ __forceinline__ void mma_f16(float* d, const uint32_t* a, const uint32_t* b) {
    asm volatile(
        "mma.sync.aligned.m16n8k16.row.col.f32.f16.f16.f32 "
        "{%0,%1,%2,%3}, {%4,%5,%6,%7}, {%8,%9}, {%0,%1,%2,%3};"
        : "+f"(d[0]), "+f"(d[1]), "+f"(d[2]), "+f"(d[3])
        : "r"(a[0]), "r"(a[1]), "r"(a[2]), "r"(a[3]), "r"(b[0]), "r"(b[1]));
}

// pack 2 fp32 -> f16x2 (rn), k-even in LOW half
__device__ __forceinline__ uint32_t pack2(float v0, float v1) {
    uint32_t h;
    asm("cvt.rn.f16x2.f32 %0, %1, %2;" : "=r"(h) : "f"(v1), "f"(v0));
    return h;
}

// split 2 fp32 -> f16x2 hi + f16x2 lo (exact residual)
__device__ __forceinline__ void split2(float v0, float v1, uint32_t& hi, uint32_t& lo) {
    uint32_t h = pack2(v0, v1);
    __half2 hh = *reinterpret_cast<__half2*>(&h);
    float f0 = __low2float(hh);
    float f1 = __high2float(hh);
    lo = pack2(v0 - f0, v1 - f1);
    hi = h;
}

// ======================= GEMM kernel =======================
// gates = xh @ (wh + wl)^T ; g_A = log(max(gates, 1e-6))
// frag layout (verified rounds 6-14): A [k2][mt 16][slot^2k2][ea], B [k2][nt 8][slot^2k2][eb]
__global__ void __launch_bounds__(NTHREADS, 1)
gemm_log_kernel(const float* __restrict__ x, const float* __restrict__ w)
{
    extern __shared__ uint32_t sm[];
    const int tid  = threadIdx.x;
    const int lane = tid & 31;
    const int wid  = tid >> 5;               // 0..7
    const int warp_m = wid >> 1;             // 0..3 -> rows warp_m*64 (4 mt tiles)
    const int warp_n = wid & 1;              // 0..1 -> cols warp_n*32 (4 nt tiles)
    const int m0 = blockIdx.x * BM;

    // loader geometry: 8 float4-cols (KC=32) x 32 row-groups
    const int col4 = tid & 7;
    const int rowg = tid >> 3;               // 0..31
    const float* xp = x + (size_t)(m0 + rowg) * K_DIM + col4 * 4;
    const float* wp = w + (size_t)rowg * K_DIM + col4 * 4;

    // converter fragment coords
    const int kk     = col4 >> 2;
    const int qp     = (col4 & 3) * 2;
    const int q      = qp & 3;
    const int khibit = qp >> 2;
    const int swz    = 2 * kk;

    float4 xv[8], wv[2];
    auto ldg = [&](int kb) {
        const float* a = xp + kb * KC;
        const float* b = wp + kb * KC;
#pragma unroll
        for (int i = 0; i < 8; i++)
            xv[i] = *reinterpret_cast<const float4*>(a + (size_t)(32 * i) * K_DIM);
#pragma unroll
        for (int i = 0; i < 2; i++)
            wv[i] = *reinterpret_cast<const float4*>(b + (size_t)(32 * i) * K_DIM);
    };

    auto sts = [&](uint32_t* fg) {
        // x -> A hi only (8 rows per thread: rowg + 32*i)
#pragma unroll
        for (int i = 0; i < 8; i++) {
            const int m = rowg + 32 * i;
            const int g = m & 7, mt = m >> 4, rowbit = (m >> 3) & 1;
            const int ea = rowbit + 2 * khibit;
            const int s0 = (g * 4 + q) ^ swz;
            const int base = ((kk * 16 + mt) * 32 + s0) * 4 + ea;
            fg[F_AH + base]     = pack2(xv[i].x, xv[i].y);
            fg[F_AH + base + 4] = pack2(xv[i].z, xv[i].w);
        }
        // w -> B hi/lo (2 rows per thread)
#pragma unroll
        for (int i = 0; i < 2; i++) {
            const int n = rowg + 32 * i;
            const int g = n & 7, nt = n >> 3;
            const int s0 = (g * 4 + q) ^ swz;
            uint32_t h0, l0, h1, l1;
            split2(wv[i].x, wv[i].y, h0, l0);
            split2(wv[i].z, wv[i].w, h1, l1);
            const int base = ((kk * 8 + nt) * 32 + s0) * 2 + khibit;
            fg[F_BH + base]     = h0;
            fg[F_BH + base + 2] = h1;
            fg[F_BL + base]     = l0;
            fg[F_BL + base + 2] = l1;
        }
    };

    float acc[4][4][4];
#pragma unroll
    for (int i = 0; i < 4; i++)
#pragma unroll
        for (int j = 0; j < 4; j++)
#pragma unroll
            for (int e = 0; e < 4; e++) acc[i][j][e] = 0.f;

    auto mma_stage = [&](const uint32_t* fg) {
#pragma unroll
        for (int k2 = 0; k2 < 2; k2++) {
            const int sl = lane ^ (2 * k2);
            uint4 ah[4];
#pragma unroll
            for (int i = 0; i < 4; i++) {
                const int mt = warp_m * 4 + i;
                ah[i] = *reinterpret_cast<const uint4*>(&fg[F_AH + ((k2 * 16 + mt) * 32 + sl) * 4]);
            }
            uint2 bh[4], bl[4];
#pragma unroll
            for (int j = 0; j < 4; j++) {
                const int nt = warp_n * 4 + j;
                bh[j] = *reinterpret_cast<const uint2*>(&fg[F_BH + ((k2 * 8 + nt) * 32 + sl) * 2]);
                bl[j] = *reinterpret_cast<const uint2*>(&fg[F_BL + ((k2 * 8 + nt) * 32 + sl) * 2]);
            }
#pragma unroll
            for (int i = 0; i < 4; i++)
#pragma unroll
                for (int j = 0; j < 4; j++) {
                    mma_f16(acc[i][j], (const uint32_t*)&ah[i], (const uint32_t*)&bl[j]);
                    mma_f16(acc[i][j], (const uint32_t*)&ah[i], (const uint32_t*)&bh[j]);
                }
        }
    };

    // ---- pipeline (R12-verified ring: regs hold kb+1; frag[kb&1] holds kb) ----
    ldg(0);
    sts(sm);              // chunk 0 -> buf 0
    ldg(1);               // chunk 1 -> regs
    __syncthreads();

    for (int kb = 0; kb < NCHUNK; kb++) {
        if (kb + 1 < NCHUNK) sts(sm + ((kb + 1) & 1) * STAGE_U);  // regs(kb+1) -> other buf
        if (kb + 2 < NCHUNK) ldg(kb + 2);                         // next chunk -> regs
        mma_stage(sm + (kb & 1) * STAGE_U);
        __syncthreads();
    }

    // epilogue: A = log(clip(gate, eps))
    const int gq = lane >> 2, qq = lane & 3;
#pragma unroll
    for (int i = 0; i < 4; i++) {
#pragma unroll
        for (int j = 0; j < 4; j++) {
            const int row0 = m0 + warp_m * 64 + i * 16 + gq;
            const int col  = warp_n * 32 + j * 8 + qq * 2;
            float2 v0, v1;
            v0.x = __logf(fmaxf(acc[i][j][0], 1e-6f));
            v0.y = __logf(fmaxf(acc[i][j][1], 1e-6f));
            v1.x = __logf(fmaxf(acc[i][j][2], 1e-6f));
            v1.y = __logf(fmaxf(acc[i][j][3], 1e-6f));
            *reinterpret_cast<float2*>(&g_A[(size_t)row0 * E_DIM + col]) = v0;
            *reinterpret_cast<float2*>(&g_A[(size_t)(row0 + 8) * E_DIM + col]) = v1;
        }
    }
}

// ======================= persistent Sinkhorn =======================
__device__ __forceinline__ void grid_barrier()
{
    __syncthreads();
    if (threadIdx.x == 0) {
        unsigned int my = g_gen;
        __threadfence();
        if (atomicAdd(&g_count, 1u) == SK_GRID - 1) {
            g_count = 0;
            __threadfence();
            g_gen = my + 1;
        } else {
            while (g_gen == my) { __nanosleep(32); }
        }
        __threadfence();
    }
    __syncthreads();
}

// Invariant: t = A - r[row] - c[e].
__global__ void __launch_bounds__(256, 2)
sinkhorn_kernel(float* __restrict__ out)
{
    extern __shared__ float sA[];            // ROWS_PB * 64 = 32 KB
    __shared__ float r_s[ROWS_PB];
    __shared__ float c_s[E_DIM];
    __shared__ float pm[4 * E_DIM];
    __shared__ float ps[4 * E_DIM];

    const int tid = threadIdx.x;
    const int b   = blockIdx.x / BLK_PER_BATCH;
    const size_t base = (size_t)blockIdx.x * ROWS_PB * E_DIM;

    for (int idx = tid; idx < ROWS_PB * E_DIM; idx += 256)
        sA[idx] = g_A[base + idx];
    if (tid < ROWS_PB) r_s[tid] = 0.f;
    __syncthreads();

    const int e   = tid & 63;
    const int grp = tid >> 6;                // 0..3 -> 32-row slice
    const int row2  = tid >> 1;
    const int half  = tid & 1;

    for (int it = 0; it < N_ITERS; it++) {
        float* part = g_part[it & 1];

        // step 1: per-expert partial LSE over 32-row slice of (A - r)
        {
            const int r0 = grp * 32;
            float M0 = -1e30f, M1 = -1e30f;
#pragma unroll 4
            for (int rr = 0; rr < 32; rr += 2) {
                M0 = fmaxf(M0, sA[(r0 + rr) * 64 + e]     - r_s[r0 + rr]);
                M1 = fmaxf(M1, sA[(r0 + rr + 1) * 64 + e] - r_s[r0 + rr + 1]);
            }
            float M = fmaxf(M0, M1);
            float S0 = 0.f, S1 = 0.f;
#pragma unroll 4
            for (int rr = 0; rr < 32; rr += 2) {
                S0 += __expf(sA[(r0 + rr) * 64 + e]     - r_s[r0 + rr]     - M);
                S1 += __expf(sA[(r0 + rr + 1) * 64 + e] - r_s[r0 + rr + 1] - M);
            }
            pm[grp * 64 + e] = M;
            ps[grp * 64 + e] = S0 + S1;
        }
        __syncthreads();
        if (tid < 64) {
            float M = pm[tid], S = ps[tid];
#pragma unroll
            for (int g2 = 1; g2 < 4; g2++) {
                float m2 = pm[g2 * 64 + tid], s2 = ps[g2 * 64 + tid];
                float nm = fmaxf(M, m2);
                S = S * __expf(M - nm) + s2 * __expf(m2 - nm);
                M = nm;
            }
            part[(blockIdx.x * 64 + tid) * 2 + 0] = M;
            part[(blockIdx.x * 64 + tid) * 2 + 1] = S;
        }
        grid_barrier();

        // combine c over the 64 blocks of this batch (grp handles 16 each)
        {
            float M = -1e30f, S = 0.f;
#pragma unroll
            for (int kk2 = 0; kk2 < 16; kk2++) {
                int blk = b * BLK_PER_BATCH + grp * 16 + kk2;
                float m2 = part[(blk * 64 + e) * 2 + 0];
                float s2 = part[(blk * 64 + e) * 2 + 1];
                float nm = fmaxf(M, m2);
                S = S * __expf(M - nm) + s2 * __expf(m2 - nm);
                M = nm;
            }
            pm[grp * 64 + e] = M;
            ps[grp * 64 + e] = S;
        }
        __syncthreads();
        if (tid < 64) {
            float M = pm[tid], S = ps[tid];
#pragma unroll
            for (int g2 = 1; g2 < 4; g2++) {
                float m2 = pm[g2 * 64 + tid], s2 = ps[g2 * 64 + tid];
                float nm = fmaxf(M, m2);
                S = S * __expf(M - nm) + s2 * __expf(m2 - nm);
                M = nm;
            }
            c_s[tid] = M + __logf(S);
        }
        __syncthreads();

        // step 2: r[row] = LSE_e(A - c); thread pair splits the 64 experts
        {
            const float* rowp = &sA[row2 * 64];
            float M = -1e30f;
#pragma unroll 8
            for (int j = 0; j < 32; j++) {
                int e2 = (half * 32 + j + row2) & 63;
                M = fmaxf(M, rowp[e2] - c_s[e2]);
            }
            float S = 0.f;
#pragma unroll 8
            for (int j = 0; j < 32; j++) {
                int e2 = (half * 32 + j + row2) & 63;
                S += __expf(rowp[e2] - c_s[e2] - M);
            }
            float om = __shfl_xor_sync(0xFFFFFFFFu, M, 1);
            float os = __shfl_xor_sync(0xFFFFFFFFu, S, 1);
            float nm = fmaxf(M, om);
            S = S * __expf(M - nm) + os * __expf(om - nm);
            r_s[row2] = nm + __logf(S);
        }
        __syncthreads();
    }

    // final: out = exp(A - r - c)
    for (int idx = tid; idx < ROWS_PB * E_DIM; idx += 256) {
        int row = idx >> 6, ee = idx & 63;
        out[base + idx] = __expf(sA[idx] - r_s[row] - c_s[ee]);
    }
}

// noop: shifts ncu capture parity so the GEMM gets profiled
__global__ void noop_kernel() {}

// ======================= launch =======================
extern "C" void kernel_launch(void* const* d_in, const int* in_sizes, int n_in,
                              void* d_out, int out_size)
{
    (void)in_sizes; (void)n_in; (void)out_size;
    const float* x = (const float*)d_in[0];       // [4,8192,4096] fp32
    const float* w = (const float*)d_in[1];       // [64,4096] fp32
    float* out = (float*)d_out;                   // [4,8192,64] fp32

    cudaFuncSetAttribute(gemm_log_kernel,
                         cudaFuncAttributeMaxDynamicSharedMemorySize, GEMM_SMEM);
    gemm_log_kernel<<<GEMM_GRID, NTHREADS, GEMM_SMEM>>>(x, w);

    cudaFuncSetAttribute(sinkhorn_kernel,
                         cudaFuncAttributeMaxDynamicSharedMemorySize,
                         ROWS_PB * E_DIM * (int)sizeof(float));
    sinkhorn_kernel<<<SK_GRID, 256, ROWS_PB * E_DIM * sizeof(float)>>>(out);

    noop_kernel<<<1, 32>>>();
}